// round 2
// baseline (speedup 1.0000x reference)
#include <cuda_runtime.h>
#include <cuda_bf16.h>

// PJCLoss: out = mean( (rec3d[b,h,w,idx[b]] - in2d[b,h,w])^2 )
// B=16, H=W=D=256.  HW = 1<<16, HWD per batch = 1<<24, total elems = 1<<20.
//
// Single kernel, 512 blocks x 256 threads. Each thread handles 8 consecutive
// (h,w) positions: two float4 loads of input_2d (coalesced) + 8 independent
// stride-1024B gather loads of rec3d (MLP=8, front-batched by ptxas).
// Block partials -> __device__ scratch; last block (fence+counter) reduces
// the 512 partials in a fixed order and writes sum/2^20. Counter is reset by
// the last block so the kernel is graph-replay safe and deterministic.
//
// slice_idx dtype defense: reference declares int64 but JAX w/o x64 emits
// int32. First 64 bytes read as 16 int32 words is valid under both layouts;
// int64 (values < 256, little-endian) => all odd words zero. Odd words all
// zero under int32 has prob ~2^-64.

#define NBLK 512

__device__ float         g_partials[NBLK];
__device__ unsigned int  g_count = 0;

__global__ __launch_bounds__(256, 8)
void pjc_loss_kernel(const float* __restrict__ rec,
                     const float* __restrict__ in2d,
                     const int*   __restrict__ idx32,
                     float*       __restrict__ out)
{
    const int bb    = blockIdx.x;
    const int b     = bb >> 5;        // 32 blocks per batch
    const int chunk = bb & 31;        // which 2048-element chunk of HW

    // --- decode slice index (int32 vs int64 heuristic) ---
    bool is64 = true;
#pragma unroll
    for (int i = 0; i < 8; i++)
        if (idx32[2 * i + 1] != 0) is64 = false;
    const int d = is64 ? idx32[2 * b] : idx32[b];

    const size_t base3d = ((size_t)b << 24) + (size_t)d;   // rec[b,0,0,d]
    const int    hw0    = (chunk << 11) + ((int)threadIdx.x << 3); // 8 per thread

    // coalesced loads of input_2d
    const float4 ga = *reinterpret_cast<const float4*>(
        in2d + ((size_t)b << 16) + hw0);
    const float4 gb = *reinterpret_cast<const float4*>(
        in2d + ((size_t)b << 16) + hw0 + 4);

    // 8 independent scattered gathers (stride 256 floats = 1024 B)
    float r[8];
#pragma unroll
    for (int i = 0; i < 8; i++)
        r[i] = __ldg(rec + base3d + ((size_t)(hw0 + i) << 8));

    float d0 = r[0] - ga.x, d1 = r[1] - ga.y, d2 = r[2] - ga.z, d3 = r[3] - ga.w;
    float d4 = r[4] - gb.x, d5 = r[5] - gb.y, d6 = r[6] - gb.z, d7 = r[7] - gb.w;

    float s = d0 * d0;
    s = fmaf(d1, d1, s);
    s = fmaf(d2, d2, s);
    s = fmaf(d3, d3, s);
    s = fmaf(d4, d4, s);
    s = fmaf(d5, d5, s);
    s = fmaf(d6, d6, s);
    s = fmaf(d7, d7, s);

    // --- warp reduce ---
#pragma unroll
    for (int off = 16; off > 0; off >>= 1)
        s += __shfl_xor_sync(0xFFFFFFFFu, s, off);

    // --- block reduce across 8 warps ---
    __shared__ float warp_sums[8];
    const int lane = threadIdx.x & 31;
    const int wid  = threadIdx.x >> 5;
    if (lane == 0) warp_sums[wid] = s;
    __syncthreads();

    __shared__ bool s_last;
    if (threadIdx.x == 0) {
        float v = warp_sums[0];
#pragma unroll
        for (int i = 1; i < 8; i++) v += warp_sums[i];
        g_partials[bb] = v;
        __threadfence();                               // partial visible chip-wide
        unsigned int prev = atomicAdd(&g_count, 1u);
        s_last = (prev == NBLK - 1);
    }
    __syncthreads();

    // --- last block reduces all partials (fixed order => deterministic) ---
    if (s_last) {
        float v = 0.0f;
        // 512 partials, 256 threads: 2 each
        v += g_partials[threadIdx.x];
        v += g_partials[threadIdx.x + 256];

#pragma unroll
        for (int off = 16; off > 0; off >>= 1)
            v += __shfl_xor_sync(0xFFFFFFFFu, v, off);

        __shared__ float fin[8];
        if (lane == 0) fin[wid] = v;
        __syncthreads();

        if (threadIdx.x == 0) {
            float t = fin[0];
#pragma unroll
            for (int i = 1; i < 8; i++) t += fin[i];
            out[0] = t * (1.0f / 1048576.0f);
            g_count = 0;                               // reset for next replay
        }
    }
}

extern "C" void kernel_launch(void* const* d_in, const int* in_sizes, int n_in,
                              void* d_out, int out_size)
{
    const float* rec   = (const float*)d_in[0];   // [16,256,256,256] f32
    const float* in2d  = (const float*)d_in[1];   // [16,256,256] f32
    const int*   idx32 = (const int*)d_in[2];     // int32 or int64 (decoded in-kernel)
    float*       out   = (float*)d_out;

    pjc_loss_kernel<<<NBLK, 256>>>(rec, in2d, idx32, out);
}

// round 4
// speedup vs baseline: 1.0816x; 1.0816x over previous
#include <cuda_runtime.h>
#include <cuda_bf16.h>

// PJCLoss: out = mean( (rec3d[b,h,w,idx[b]] - in2d[b,h,w])^2 )
// B=16, H=W=D=256.  HW = 1<<16, HWD per batch = 1<<24, total elems = 1<<20.
//
// R2 measured 142 MB DRAM traffic = ~128 B per 4 B gather (full L2 line fill),
// 27.1 us @ 4755 GB/s. R3/R4 change (single variable): gather loads use
// ld.global.cs (__ldcs, streaming/evict-first) to avoid 128B line promotion
// and fetch only touched sectors. Everything else unchanged for clean A/B.
//
// Single kernel, 512 blocks x 256 threads, 8 elements/thread (MLP=8).
// Block partials -> __device__ scratch; last block (fence+counter) reduces
// in fixed order => deterministic; counter self-resets => graph-replay safe.
//
// slice_idx dtype defense: reference declares int64 but JAX w/o x64 emits
// int32. First 64 bytes read as 16 int32 words is valid under both layouts;
// int64 (values < 256, little-endian) => all odd words zero.

#define NBLK 512

__device__ float         g_partials[NBLK];
__device__ unsigned int  g_count = 0;

__global__ __launch_bounds__(256, 8)
void pjc_loss_kernel(const float* __restrict__ rec,
                     const float* __restrict__ in2d,
                     const int*   __restrict__ idx32,
                     float*       __restrict__ out)
{
    const int bb    = blockIdx.x;
    const int b     = bb >> 5;        // 32 blocks per batch
    const int chunk = bb & 31;        // which 2048-element chunk of HW

    // --- decode slice index (int32 vs int64 heuristic) ---
    bool is64 = true;
#pragma unroll
    for (int i = 0; i < 8; i++)
        if (idx32[2 * i + 1] != 0) is64 = false;
    const int d = is64 ? idx32[2 * b] : idx32[b];

    const size_t base3d = ((size_t)b << 24) + (size_t)d;   // rec[b,0,0,d]
    const int    hw0    = (chunk << 11) + ((int)threadIdx.x << 3); // 8 per thread

    // coalesced loads of input_2d
    const float4 ga = *reinterpret_cast<const float4*>(
        in2d + ((size_t)b << 16) + hw0);
    const float4 gb = *reinterpret_cast<const float4*>(
        in2d + ((size_t)b << 16) + hw0 + 4);

    // 8 independent scattered gathers (stride 256 floats = 1024 B),
    // streaming cache-op: no 128B line promotion, evict-first.
    float r[8];
#pragma unroll
    for (int i = 0; i < 8; i++)
        r[i] = __ldcs(rec + base3d + ((size_t)(hw0 + i) << 8));

    float d0 = r[0] - ga.x, d1 = r[1] - ga.y, d2 = r[2] - ga.z, d3 = r[3] - ga.w;
    float d4 = r[4] - gb.x, d5 = r[5] - gb.y, d6 = r[6] - gb.z, d7 = r[7] - gb.w;

    float s = d0 * d0;
    s = fmaf(d1, d1, s);
    s = fmaf(d2, d2, s);
    s = fmaf(d3, d3, s);
    s = fmaf(d4, d4, s);
    s = fmaf(d5, d5, s);
    s = fmaf(d6, d6, s);
    s = fmaf(d7, d7, s);

    // --- warp reduce ---
#pragma unroll
    for (int off = 16; off > 0; off >>= 1)
        s += __shfl_xor_sync(0xFFFFFFFFu, s, off);

    // --- block reduce across 8 warps ---
    __shared__ float warp_sums[8];
    const int lane = threadIdx.x & 31;
    const int wid  = threadIdx.x >> 5;
    if (lane == 0) warp_sums[wid] = s;
    __syncthreads();

    __shared__ bool s_last;
    if (threadIdx.x == 0) {
        float v = warp_sums[0];
#pragma unroll
        for (int i = 1; i < 8; i++) v += warp_sums[i];
        g_partials[bb] = v;
        __threadfence();                               // partial visible chip-wide
        unsigned int prev = atomicAdd(&g_count, 1u);
        s_last = (prev == NBLK - 1);
    }
    __syncthreads();

    // --- last block reduces all partials (fixed order => deterministic) ---
    if (s_last) {
        float v = 0.0f;
        v += g_partials[threadIdx.x];
        v += g_partials[threadIdx.x + 256];

#pragma unroll
        for (int off = 16; off > 0; off >>= 1)
            v += __shfl_xor_sync(0xFFFFFFFFu, v, off);

        __shared__ float fin[8];
        if (lane == 0) fin[wid] = v;
        __syncthreads();

        if (threadIdx.x == 0) {
            float t = fin[0];
#pragma unroll
            for (int i = 1; i < 8; i++) t += fin[i];
            out[0] = t * (1.0f / 1048576.0f);
            g_count = 0;                               // reset for next replay
        }
    }
}

extern "C" void kernel_launch(void* const* d_in, const int* in_sizes, int n_in,
                              void* d_out, int out_size)
{
    const float* rec   = (const float*)d_in[0];   // [16,256,256,256] f32
    const float* in2d  = (const float*)d_in[1];   // [16,256,256] f32
    const int*   idx32 = (const int*)d_in[2];     // int32 or int64 (decoded in-kernel)
    float*       out   = (float*)d_out;

    pjc_loss_kernel<<<NBLK, 256>>>(rec, in2d, idx32, out);
}